// round 1
// baseline (speedup 1.0000x reference)
#include <cuda_runtime.h>
#include <math.h>

#define Bb   8
#define Ls   1024
#define DM   256
#define DIc  512
#define NT   (Bb*Ls)      // 8192 tokens
#define CS   64           // scan chunk size
#define NC   (Ls/CS)      // 16 chunks
#define DSn  16

// ---------------- scratch (static device memory; no runtime allocs) ----------------
__device__ float g_featA[NT*DM];
__device__ float g_featB[NT*DM];
__device__ float g_xz  [NT*2*DIc];
__device__ float g_xs  [NT*DIc];
__device__ float g_dbl [NT*48];
__device__ float g_dtv [NT*DIc];
__device__ float g_y   [NT*DIc];
__device__ float g_yF  [NT*DM];
__device__ float g_yB  [NT*DM];
__device__ float g_hend [Bb*DIc*NC*DSn];
__device__ float g_sumdt[Bb*DIc*NC];
__device__ float g_hinit[Bb*DIc*NC*DSn];

// ---------------- helpers ----------------
static __device__ __forceinline__ float siluf(float v) {
    return v / (1.f + __expf(-v));
}
static __device__ __forceinline__ float softplusf(float v) {
    // numerically safe softplus
    return fmaxf(v, 0.f) + log1pf(__expf(-fabsf(v)));
}

// block reduce over 256 threads (8 warps)
static __device__ __forceinline__ float block_reduce_sum256(float v, float* sh) {
    int tid = threadIdx.x;
    #pragma unroll
    for (int o = 16; o > 0; o >>= 1) v += __shfl_down_sync(0xffffffffu, v, o);
    if ((tid & 31) == 0) sh[tid >> 5] = v;
    __syncthreads();
    if (tid < 8) {
        v = sh[tid];
        #pragma unroll
        for (int o = 4; o > 0; o >>= 1) v += __shfl_down_sync(0xffu, v, o);
        if (tid == 0) sh[0] = v;
    }
    __syncthreads();
    float r = sh[0];
    __syncthreads();
    return r;
}

// ---------------- embedding + fusion + token LN ----------------
__global__ __launch_bounds__(256) void k_embed(
    const float* __restrict__ x,
    const float* __restrict__ ep, const float* __restrict__ ef, const float* __restrict__ ed,
    const float* __restrict__ lw, const float* __restrict__ lb,
    const float* __restrict__ iw, const float* __restrict__ ib,
    const float* __restrict__ fw, const float* __restrict__ fb,
    const float* __restrict__ tg, const float* __restrict__ tb,
    float* __restrict__ feat)
{
    int bt = blockIdx.x;
    int tid = threadIdx.x;
    __shared__ float c[136];
    __shared__ float red[8];
    const float* xr = x + (size_t)bt * 5;
    if (tid < 136) {
        float v;
        if (tid < 32) {
            int p = (int)xr[0]; p = p < 0 ? 0 : (p > 255 ? 255 : p);
            v = ep[p*32 + tid];
        } else if (tid < 64) {
            int e = tid - 32;
            v = xr[1]*lw[e] + lb[e];
        } else if (tid < 96) {
            int f = (int)xr[2]; f = f < 0 ? 0 : (f > 63 ? 63 : f);
            v = ef[f*32 + (tid - 64)];
        } else if (tid < 128) {
            int e = tid - 96;
            v = xr[3]*iw[e] + ib[e];
        } else {
            int dr = (int)xr[4]; dr = dr < 0 ? 0 : (dr > 1 ? 1 : dr);
            v = ed[dr*8 + (tid - 128)];
        }
        c[tid] = v;
    }
    __syncthreads();
    float acc = fb[tid];
    const float* wr = fw + (size_t)tid * 136;
    #pragma unroll 8
    for (int k = 0; k < 136; k++) acc += c[k] * wr[k];
    float s = block_reduce_sum256(acc, red);
    float m = s * (1.f/256.f);
    float dv = acc - m;
    float q = block_reduce_sum256(dv*dv, red);
    float inv = rsqrtf(q * (1.f/256.f) + 1e-5f);
    feat[(size_t)bt*DM + tid] = dv * inv * tg[tid] + tb[tid];
}

// ---------------- generic SGEMM: C[M,N] = A[M,K] * W[N,K]^T ----------------
__global__ __launch_bounds__(256) void sgemm_nt(
    const float* __restrict__ A, const float* __restrict__ W,
    float* __restrict__ C, int M, int N, int K)
{
    __shared__ __align__(16) float As[16][68];
    __shared__ __align__(16) float Ws[16][68];
    int tid = threadIdx.x;
    int n0 = blockIdx.x * 64;
    int m0 = blockIdx.y * 64;
    int tx = tid & 15, ty = tid >> 4;
    float acc[4][4];
    #pragma unroll
    for (int i = 0; i < 4; i++)
        #pragma unroll
        for (int j = 0; j < 4; j++) acc[i][j] = 0.f;

    for (int k0 = 0; k0 < K; k0 += 16) {
        #pragma unroll
        for (int r = 0; r < 4; r++) {
            int idx = tid + r*256;
            int i = idx >> 4, j = idx & 15;
            As[j][i] = A[(size_t)(m0+i)*K + k0 + j];
            int n = n0 + i;
            Ws[j][i] = (n < N) ? W[(size_t)n*K + k0 + j] : 0.f;
        }
        __syncthreads();
        #pragma unroll
        for (int kk = 0; kk < 16; kk++) {
            float4 av = *(const float4*)&As[kk][ty<<2];
            float4 wv = *(const float4*)&Ws[kk][tx<<2];
            float aa[4] = {av.x, av.y, av.z, av.w};
            float ww[4] = {wv.x, wv.y, wv.z, wv.w};
            #pragma unroll
            for (int i = 0; i < 4; i++)
                #pragma unroll
                for (int j = 0; j < 4; j++) acc[i][j] += aa[i]*ww[j];
        }
        __syncthreads();
    }
    #pragma unroll
    for (int i = 0; i < 4; i++) {
        int m = m0 + (ty<<2) + i;
        #pragma unroll
        for (int j = 0; j < 4; j++) {
            int n = n0 + (tx<<2) + j;
            if (n < N) C[(size_t)m*N + n] = acc[i][j];
        }
    }
}

// ---------------- depthwise causal/anticausal conv + silu ----------------
__global__ __launch_bounds__(256) void k_conv(
    const float* __restrict__ xz, const float* __restrict__ cw,
    const float* __restrict__ cb, float* __restrict__ xs, int rev)
{
    int idx = blockIdx.x * 256 + threadIdx.x;   // over NT*DIc
    int d = idx & 511;
    int bt = idx >> 9;
    int b = bt >> 10, t = bt & 1023;
    float w0 = cw[d*4+0], w1 = cw[d*4+1], w2 = cw[d*4+2], w3 = cw[d*4+3];
    float acc = cb[d];
    const float* base = xz + (size_t)(b << 10) * 1024 + d;
    if (!rev) {
        if (t >= 3) acc += base[(size_t)(t-3)*1024] * w0;
        if (t >= 2) acc += base[(size_t)(t-2)*1024] * w1;
        if (t >= 1) acc += base[(size_t)(t-1)*1024] * w2;
        acc += base[(size_t)t*1024] * w3;
    } else {
        acc += base[(size_t)t*1024] * w3;
        if (t+1 < 1024) acc += base[(size_t)(t+1)*1024] * w2;
        if (t+2 < 1024) acc += base[(size_t)(t+2)*1024] * w1;
        if (t+3 < 1024) acc += base[(size_t)(t+3)*1024] * w0;
    }
    xs[(size_t)bt*DIc + d] = siluf(acc);
}

// ---------------- dt projection + softplus (16 tokens per block) ----------------
__global__ __launch_bounds__(512) void k_dt(
    const float* __restrict__ dbl, const float* __restrict__ dtw,
    const float* __restrict__ dtbias, float* __restrict__ dto)
{
    __shared__ float dsh[16][16];
    int t0 = blockIdx.x * 16;
    int tid = threadIdx.x;
    if (tid < 256) {
        int i = tid >> 4, r = tid & 15;
        dsh[i][r] = dbl[(size_t)(t0+i)*48 + r];
    }
    __syncthreads();
    const float* wp = dtw + (size_t)tid * 16;
    float4 w0 = *(const float4*)(wp);
    float4 w1 = *(const float4*)(wp+4);
    float4 w2 = *(const float4*)(wp+8);
    float4 w3 = *(const float4*)(wp+12);
    float bia = dtbias[tid];
    #pragma unroll
    for (int i = 0; i < 16; i++) {
        const float* ds = dsh[i];
        float a = bia;
        a += ds[0]*w0.x + ds[1]*w0.y + ds[2]*w0.z + ds[3]*w0.w;
        a += ds[4]*w1.x + ds[5]*w1.y + ds[6]*w1.z + ds[7]*w1.w;
        a += ds[8]*w2.x + ds[9]*w2.y + ds[10]*w2.z + ds[11]*w2.w;
        a += ds[12]*w3.x + ds[13]*w3.y + ds[14]*w3.z + ds[15]*w3.w;
        dto[(size_t)(t0+i)*DIc + tid] = softplusf(a);
    }
}

// ---------------- selective scan: pass 1 (per-chunk local scan) ----------------
__global__ __launch_bounds__(128) void k_scan1(
    const float* __restrict__ dt, const float* __restrict__ xs,
    const float* __restrict__ dbl, const float* __restrict__ alog,
    float* __restrict__ hend, float* __restrict__ sumdt, int rev)
{
    int d = blockIdx.x * 128 + threadIdx.x;
    int c = blockIdx.y, b = blockIdx.z;
    __shared__ float Bsh[CS][16];
    int s0 = c * CS;
    for (int idx = threadIdx.x; idx < CS*16; idx += 128) {
        int i = idx >> 4, n = idx & 15;
        int t = rev ? (1023 - (s0+i)) : (s0+i);
        Bsh[i][n] = dbl[(size_t)(b*1024 + t)*48 + 16 + n];
    }
    __syncthreads();
    float A[16];
    #pragma unroll
    for (int n = 0; n < 16; n++) A[n] = -__expf(alog[(size_t)d*16 + n]);
    float h[16];
    #pragma unroll
    for (int n = 0; n < 16; n++) h[n] = 0.f;
    float sd = 0.f;
    for (int i = 0; i < CS; i++) {
        int t = rev ? (1023 - (s0+i)) : (s0+i);
        size_t off = (size_t)(b*1024 + t)*DIc + d;
        float dtv = dt[off];
        float xv  = xs[off];
        float w = dtv * xv;
        sd += dtv;
        #pragma unroll
        for (int n = 0; n < 16; n++)
            h[n] = __expf(dtv * A[n]) * h[n] + w * Bsh[i][n];
    }
    int bd = b*DIc + d;
    sumdt[(size_t)bd*NC + c] = sd;
    #pragma unroll
    for (int n = 0; n < 16; n++)
        hend[((size_t)bd*NC + c)*16 + n] = h[n];
}

// ---------------- selective scan: pass 2 (chunk carry) ----------------
__global__ __launch_bounds__(256) void k_scan2(
    const float* __restrict__ hend, const float* __restrict__ sumdt,
    const float* __restrict__ alog, float* __restrict__ hinit)
{
    int bd = blockIdx.x * 256 + threadIdx.x;   // 4096
    int d = bd & 511;
    float A[16];
    #pragma unroll
    for (int n = 0; n < 16; n++) A[n] = -__expf(alog[(size_t)d*16 + n]);
    float H[16];
    #pragma unroll
    for (int n = 0; n < 16; n++) H[n] = 0.f;
    for (int c = 0; c < NC; c++) {
        #pragma unroll
        for (int n = 0; n < 16; n++)
            hinit[((size_t)bd*NC + c)*16 + n] = H[n];
        float sd = sumdt[(size_t)bd*NC + c];
        #pragma unroll
        for (int n = 0; n < 16; n++)
            H[n] = __expf(A[n]*sd) * H[n] + hend[((size_t)bd*NC + c)*16 + n];
    }
}

// ---------------- selective scan: pass 3 (rescan + fused gate epilogue) ----------------
__global__ __launch_bounds__(128) void k_scan3(
    const float* __restrict__ dt, const float* __restrict__ xs,
    const float* __restrict__ dbl, const float* __restrict__ xz,
    const float* __restrict__ alog, const float* __restrict__ dp,
    const float* __restrict__ hinit, float* __restrict__ y, int rev)
{
    int d = blockIdx.x * 128 + threadIdx.x;
    int c = blockIdx.y, b = blockIdx.z;
    __shared__ float sh[CS][32];   // [i][0..15]=B, [i][16..31]=C
    int s0 = c * CS;
    for (int idx = threadIdx.x; idx < CS*32; idx += 128) {
        int i = idx >> 5, q = idx & 31;
        int t = rev ? (1023 - (s0+i)) : (s0+i);
        sh[i][q] = dbl[(size_t)(b*1024 + t)*48 + 16 + q];
    }
    __syncthreads();
    float A[16];
    #pragma unroll
    for (int n = 0; n < 16; n++) A[n] = -__expf(alog[(size_t)d*16 + n]);
    int bd = b*DIc + d;
    float h[16];
    #pragma unroll
    for (int n = 0; n < 16; n++) h[n] = hinit[((size_t)bd*NC + c)*16 + n];
    float dpd = dp[d];
    for (int i = 0; i < CS; i++) {
        int t = rev ? (1023 - (s0+i)) : (s0+i);
        size_t off = (size_t)(b*1024 + t)*DIc + d;
        float dtv = dt[off];
        float xv  = xs[off];
        float w = dtv * xv;
        float yv = 0.f;
        #pragma unroll
        for (int n = 0; n < 16; n++) {
            h[n] = __expf(dtv * A[n]) * h[n] + w * sh[i][n];
            yv += h[n] * sh[i][16 + n];
        }
        float zv = xz[(size_t)(b*1024 + t)*1024 + 512 + d];
        y[off] = (yv + dpd * xv) * siluf(zv);
    }
}

// ---------------- combine: dual residual LN + halve, with time-reversal fold ----------------
__global__ __launch_bounds__(256) void k_combine(
    const float* __restrict__ yF, const float* __restrict__ yB,
    const float* __restrict__ feat,
    const float* __restrict__ g, const float* __restrict__ bta,
    float* __restrict__ outf)
{
    int bt = blockIdx.x, tid = threadIdx.x;
    int b = bt >> 10, t = bt & 1023;
    int btr = (b << 10) + (1023 - t);
    __shared__ float red[8];
    float v1 = yF[(size_t)bt*DM + tid] + feat[(size_t)bt*DM + tid];
    float v2 = yB[(size_t)bt*DM + tid] + feat[(size_t)btr*DM + tid];
    float s1 = block_reduce_sum256(v1, red);
    float m1 = s1 * (1.f/256.f);
    float d1 = v1 - m1;
    float q1 = block_reduce_sum256(d1*d1, red);
    float i1 = rsqrtf(q1 * (1.f/256.f) + 1e-5f);
    float s2 = block_reduce_sum256(v2, red);
    float m2 = s2 * (1.f/256.f);
    float d2 = v2 - m2;
    float q2 = block_reduce_sum256(d2*d2, red);
    float i2 = rsqrtf(q2 * (1.f/256.f) + 1e-5f);
    outf[(size_t)bt*DM + tid] = 0.5f * (d1*i1 + d2*i2) * g[tid] + bta[tid];
}

// ---------------- final mean over L ----------------
__global__ __launch_bounds__(256) void k_mean(const float* __restrict__ feat, float* __restrict__ out) {
    int b = blockIdx.x, i = threadIdx.x;
    float s = 0.f;
    const float* p = feat + (size_t)b*1024*DM + i;
    for (int t = 0; t < 1024; t++) s += p[(size_t)t*DM];
    out[(size_t)b*DM + i] = s * (1.f/1024.f);
}

// ---------------- host launcher ----------------
extern "C" void kernel_launch(void* const* d_in, const int* in_sizes, int n_in,
                              void* d_out, int out_size) {
    const float* x         = (const float*)d_in[0];
    const float* emb_proto = (const float*)d_in[1];
    const float* emb_flags = (const float*)d_in[2];
    const float* emb_dir   = (const float*)d_in[3];
    const float* len_w     = (const float*)d_in[4];
    const float* len_b     = (const float*)d_in[5];
    const float* iat_w     = (const float*)d_in[6];
    const float* iat_b     = (const float*)d_in[7];
    const float* fus_w     = (const float*)d_in[8];
    const float* fus_b     = (const float*)d_in[9];
    const float* tok_g     = (const float*)d_in[10];
    const float* tok_b     = (const float*)d_in[11];
    const float* in_proj_w = (const float*)d_in[12];
    const float* conv_w    = (const float*)d_in[13];
    const float* conv_b    = (const float*)d_in[14];
    const float* xproj_w   = (const float*)d_in[15];
    const float* dt_w      = (const float*)d_in[16];
    const float* dt_b      = (const float*)d_in[17];
    const float* A_log     = (const float*)d_in[18];
    const float* D_p       = (const float*)d_in[19];
    const float* out_w     = (const float*)d_in[20];
    const float* norm_g    = (const float*)d_in[21];
    const float* norm_b    = (const float*)d_in[22];
    float* out = (float*)d_out;

    float *featA, *featB, *xz, *xs, *dbl, *dtb, *ybuf, *yF, *yB, *hend, *sumdt, *hinit;
    cudaGetSymbolAddress((void**)&featA, g_featA);
    cudaGetSymbolAddress((void**)&featB, g_featB);
    cudaGetSymbolAddress((void**)&xz,    g_xz);
    cudaGetSymbolAddress((void**)&xs,    g_xs);
    cudaGetSymbolAddress((void**)&dbl,   g_dbl);
    cudaGetSymbolAddress((void**)&dtb,   g_dtv);
    cudaGetSymbolAddress((void**)&ybuf,  g_y);
    cudaGetSymbolAddress((void**)&yF,    g_yF);
    cudaGetSymbolAddress((void**)&yB,    g_yB);
    cudaGetSymbolAddress((void**)&hend,  g_hend);
    cudaGetSymbolAddress((void**)&sumdt, g_sumdt);
    cudaGetSymbolAddress((void**)&hinit, g_hinit);

    k_embed<<<NT, 256>>>(x, emb_proto, emb_flags, emb_dir, len_w, len_b,
                         iat_w, iat_b, fus_w, fus_b, tok_g, tok_b, featA);

    float* cur = featA;
    float* nxt = featB;

    for (int l = 0; l < 4; l++) {
        for (int dir = 0; dir < 2; dir++) {
            int w = dir*4 + l;
            const float* ipw = in_proj_w + (size_t)w * 1024 * 256;
            const float* cw  = conv_w    + (size_t)w * DIc * 4;
            const float* cbp = conv_b    + (size_t)w * DIc;
            const float* xpw = xproj_w   + (size_t)w * 48 * DIc;
            const float* dtw = dt_w      + (size_t)w * DIc * 16;
            const float* dtbias = dt_b   + (size_t)w * DIc;
            const float* alog = A_log    + (size_t)w * DIc * DSn;
            const float* dpp  = D_p      + (size_t)w * DIc;
            const float* ow   = out_w    + (size_t)w * DM * DIc;

            sgemm_nt<<<dim3(16, 128), 256>>>(cur, ipw, xz, NT, 1024, 256);
            k_conv<<<(NT*DIc)/256, 256>>>(xz, cw, cbp, xs, dir);
            sgemm_nt<<<dim3(1, 128), 256>>>(xs, xpw, dbl, NT, 48, 512);
            k_dt<<<NT/16, 512>>>(dbl, dtw, dtbias, dtb);
            k_scan1<<<dim3(4, NC, Bb), 128>>>(dtb, xs, dbl, alog, hend, sumdt, dir);
            k_scan2<<<16, 256>>>(hend, sumdt, alog, hinit);
            k_scan3<<<dim3(4, NC, Bb), 128>>>(dtb, xs, dbl, xz, alog, dpp, hinit, ybuf, dir);
            sgemm_nt<<<dim3(4, 128), 256>>>(ybuf, ow, dir ? yB : yF, NT, 256, 512);
        }
        k_combine<<<NT, 256>>>(yF, yB, cur, norm_g, norm_b, nxt);
        float* tmp = cur; cur = nxt; nxt = tmp;
    }

    k_mean<<<Bb, 256>>>(cur, out);
}

// round 3
// speedup vs baseline: 1.3153x; 1.3153x over previous
#include <cuda_runtime.h>
#include <math.h>

#define Bb   8
#define Ls   1024
#define DM   256
#define DIc  512
#define NT   (Bb*Ls)      // 8192 tokens
#define CS   64           // scan chunk size
#define NC   (Ls/CS)      // 16 chunks
#define DSn  16

// ---------------- scratch (static device memory; no runtime allocs) ----------------
__device__ float g_featA[NT*DM];
__device__ float g_featB[NT*DM];
__device__ float g_xz  [NT*2048];      // merged dirs: cols [dir*1024 + (x:0..511 | z:512..1023)]
__device__ float g_xs  [NT*1024];      // merged dirs: cols [dir*512 + d]
__device__ float g_dbl [NT*96];        // merged dirs: cols [dir*48 + r]
__device__ float g_dtv [NT*1024];      // merged dirs
__device__ float g_y   [NT*1024];      // merged dirs
__device__ float g_yF  [NT*DM];
__device__ float g_yB  [NT*DM];
__device__ float g_hend [8192*NC*DSn]; // bdd = b*1024 + dir*512 + d
__device__ float g_sumdt[8192*NC];
__device__ float g_hinit[8192*NC*DSn];

// ---------------- helpers ----------------
static __device__ __forceinline__ float ex2f(float v) {
    float r;
    asm("ex2.approx.f32 %0, %1;" : "=f"(r) : "f"(v));
    return r;
}
static __device__ __forceinline__ float siluf(float v) {
    return v / (1.f + __expf(-v));
}
static __device__ __forceinline__ float softplusf(float v) {
    return fmaxf(v, 0.f) + log1pf(__expf(-fabsf(v)));
}
static __device__ __forceinline__ unsigned long long dup2(float w) {
    unsigned long long r;
    asm("mov.b64 %0, {%1, %1};" : "=l"(r) : "f"(w));
    return r;
}
static __device__ __forceinline__ void fma2(unsigned long long& d,
                                            unsigned long long a,
                                            unsigned long long b) {
    asm("fma.rn.f32x2 %0, %1, %2, %0;" : "+l"(d) : "l"(a), "l"(b));
}
static __device__ __forceinline__ float2 unpack2(unsigned long long v) {
    float2 f;
    asm("mov.b64 {%0, %1}, %2;" : "=f"(f.x), "=f"(f.y) : "l"(v));
    return f;
}

// block reduce over 256 threads (8 warps)
static __device__ __forceinline__ float block_reduce_sum256(float v, float* sh) {
    int tid = threadIdx.x;
    #pragma unroll
    for (int o = 16; o > 0; o >>= 1) v += __shfl_down_sync(0xffffffffu, v, o);
    if ((tid & 31) == 0) sh[tid >> 5] = v;
    __syncthreads();
    if (tid < 8) {
        v = sh[tid];
        #pragma unroll
        for (int o = 4; o > 0; o >>= 1) v += __shfl_down_sync(0xffu, v, o);
        if (tid == 0) sh[0] = v;
    }
    __syncthreads();
    float r = sh[0];
    __syncthreads();
    return r;
}

// ---------------- embedding + fusion + token LN ----------------
__global__ __launch_bounds__(256) void k_embed(
    const float* __restrict__ x,
    const float* __restrict__ ep, const float* __restrict__ ef, const float* __restrict__ ed,
    const float* __restrict__ lw, const float* __restrict__ lb,
    const float* __restrict__ iw, const float* __restrict__ ib,
    const float* __restrict__ fw, const float* __restrict__ fb,
    const float* __restrict__ tg, const float* __restrict__ tb,
    float* __restrict__ feat)
{
    int bt = blockIdx.x;
    int tid = threadIdx.x;
    __shared__ float c[136];
    __shared__ float red[8];
    const float* xr = x + (size_t)bt * 5;
    if (tid < 136) {
        float v;
        if (tid < 32) {
            int p = (int)xr[0]; p = p < 0 ? 0 : (p > 255 ? 255 : p);
            v = ep[p*32 + tid];
        } else if (tid < 64) {
            int e = tid - 32;
            v = xr[1]*lw[e] + lb[e];
        } else if (tid < 96) {
            int f = (int)xr[2]; f = f < 0 ? 0 : (f > 63 ? 63 : f);
            v = ef[f*32 + (tid - 64)];
        } else if (tid < 128) {
            int e = tid - 96;
            v = xr[3]*iw[e] + ib[e];
        } else {
            int dr = (int)xr[4]; dr = dr < 0 ? 0 : (dr > 1 ? 1 : dr);
            v = ed[dr*8 + (tid - 128)];
        }
        c[tid] = v;
    }
    __syncthreads();
    float acc = fb[tid];
    const float* wr = fw + (size_t)tid * 136;
    #pragma unroll 8
    for (int k = 0; k < 136; k++) acc += c[k] * wr[k];
    float s = block_reduce_sum256(acc, red);
    float m = s * (1.f/256.f);
    float dv = acc - m;
    float q = block_reduce_sum256(dv*dv, red);
    float inv = rsqrtf(q * (1.f/256.f) + 1e-5f);
    feat[(size_t)bt*DM + tid] = dv * inv * tg[tid] + tb[tid];
}

// ---------------- f32x2 SGEMM: C[M,N] = A[M,K] * W[N,K]^T ----------------
// 128x64 tile, 256 threads, per-thread 8x4 (4 m-pairs x 4 n) packed f32x2 accum.
// Weight rows >= nsplit come from W1 (row n-nsplit). Output cols >= csplit go to
// C1 (col n-csplit); both outputs use row stride ldc.
__global__ __launch_bounds__(256) void sgemm_f2(
    const float* __restrict__ A, int lda,
    const float* __restrict__ W0, const float* __restrict__ W1, int nsplit,
    float* __restrict__ C0, float* __restrict__ C1, int csplit, int ldc,
    int N, int K)
{
    __shared__ __align__(16) float As[16][132];
    __shared__ __align__(16) float Ws[16][68];
    int tid = threadIdx.x;
    int m0 = blockIdx.y * 128;
    int n0 = blockIdx.x * 64;
    int tx = tid & 15, ty = tid >> 4;

    // global loaders
    int arow = tid >> 1;             // 0..127
    int acol = (tid & 1) * 8;        // 0 or 8
    int wrow = tid >> 2;             // 0..63
    int wcol = (tid & 3) * 4;        // 0,4,8,12

    unsigned long long acc[4][4];
    #pragma unroll
    for (int p = 0; p < 4; p++)
        #pragma unroll
        for (int j = 0; j < 4; j++) acc[p][j] = 0ull;

    const float* Arow = A + (size_t)(m0 + arow) * lda;
    int ng = n0 + wrow;
    const float* Wrow;
    if (ng < nsplit) Wrow = W0 + (size_t)ng * K;
    else             Wrow = W1 + (size_t)(ng - nsplit) * K;
    bool wvalid = (ng < N);

    for (int k0 = 0; k0 < K; k0 += 16) {
        float4 a0 = *(const float4*)&Arow[k0 + acol];
        float4 a1 = *(const float4*)&Arow[k0 + acol + 4];
        float4 wv;
        if (wvalid) wv = *(const float4*)&Wrow[k0 + wcol];
        else        wv = make_float4(0.f, 0.f, 0.f, 0.f);
        __syncthreads();
        As[acol+0][arow] = a0.x; As[acol+1][arow] = a0.y;
        As[acol+2][arow] = a0.z; As[acol+3][arow] = a0.w;
        As[acol+4][arow] = a1.x; As[acol+5][arow] = a1.y;
        As[acol+6][arow] = a1.z; As[acol+7][arow] = a1.w;
        Ws[wcol+0][wrow] = wv.x; Ws[wcol+1][wrow] = wv.y;
        Ws[wcol+2][wrow] = wv.z; Ws[wcol+3][wrow] = wv.w;
        __syncthreads();
        #pragma unroll
        for (int kk = 0; kk < 16; kk++) {
            ulonglong2 aA = *(const ulonglong2*)&As[kk][ty*8];
            ulonglong2 aB = *(const ulonglong2*)&As[kk][ty*8 + 4];
            float4 wf = *(const float4*)&Ws[kk][tx*4];
            unsigned long long wd0 = dup2(wf.x);
            unsigned long long wd1 = dup2(wf.y);
            unsigned long long wd2 = dup2(wf.z);
            unsigned long long wd3 = dup2(wf.w);
            fma2(acc[0][0], aA.x, wd0); fma2(acc[0][1], aA.x, wd1);
            fma2(acc[0][2], aA.x, wd2); fma2(acc[0][3], aA.x, wd3);
            fma2(acc[1][0], aA.y, wd0); fma2(acc[1][1], aA.y, wd1);
            fma2(acc[1][2], aA.y, wd2); fma2(acc[1][3], aA.y, wd3);
            fma2(acc[2][0], aB.x, wd0); fma2(acc[2][1], aB.x, wd1);
            fma2(acc[2][2], aB.x, wd2); fma2(acc[2][3], aB.x, wd3);
            fma2(acc[3][0], aB.y, wd0); fma2(acc[3][1], aB.y, wd1);
            fma2(acc[3][2], aB.y, wd2); fma2(acc[3][3], aB.y, wd3);
        }
    }

    #pragma unroll
    for (int p = 0; p < 4; p++) {
        int m = m0 + ty*8 + 2*p;
        #pragma unroll
        for (int j = 0; j < 4; j++) {
            int n = n0 + tx*4 + j;
            if (n < N) {
                float2 v = unpack2(acc[p][j]);
                float* Cp; int nn;
                if (n < csplit) { Cp = C0; nn = n; }
                else            { Cp = C1; nn = n - csplit; }
                Cp[(size_t)m*ldc + nn]     = v.x;
                Cp[(size_t)(m+1)*ldc + nn] = v.y;
            }
        }
    }
}

// ---------------- depthwise causal/anticausal conv + silu (both dirs) ----------------
__global__ __launch_bounds__(256) void k_conv(
    const float* __restrict__ xz, const float* __restrict__ cwl,
    const float* __restrict__ cbl, float* __restrict__ xs)
{
    int idx = blockIdx.x * 256 + threadIdx.x;   // over NT*1024
    int d1024 = idx & 1023;
    int bt = idx >> 10;
    int dir = d1024 >> 9;
    int dd  = d1024 & 511;
    int b = bt >> 10, t = bt & 1023;
    const float* cw = cwl + dir*(4*512*4) + dd*4;
    float w0 = cw[0], w1 = cw[1], w2 = cw[2], w3 = cw[3];
    float acc = cbl[dir*(4*512) + dd];
    const float* base = xz + (size_t)(b << 10) * 2048 + dir*1024 + dd;
    if (!dir) {
        if (t >= 3) acc += base[(size_t)(t-3)*2048] * w0;
        if (t >= 2) acc += base[(size_t)(t-2)*2048] * w1;
        if (t >= 1) acc += base[(size_t)(t-1)*2048] * w2;
        acc += base[(size_t)t*2048] * w3;
    } else {
        acc += base[(size_t)t*2048] * w3;
        if (t+1 < 1024) acc += base[(size_t)(t+1)*2048] * w2;
        if (t+2 < 1024) acc += base[(size_t)(t+2)*2048] * w1;
        if (t+3 < 1024) acc += base[(size_t)(t+3)*2048] * w0;
    }
    xs[(size_t)bt*1024 + dir*512 + dd] = siluf(acc);
}

// ---------------- dt projection + softplus (both dirs) ----------------
__global__ __launch_bounds__(512) void k_dt(
    const float* __restrict__ dbl, const float* __restrict__ dtwl,
    const float* __restrict__ dtbl, float* __restrict__ dto)
{
    __shared__ float dsh[16][16];
    int t0 = blockIdx.x * 16;
    int dir = blockIdx.y;
    int tid = threadIdx.x;
    if (tid < 256) {
        int i = tid >> 4, r = tid & 15;
        dsh[i][r] = dbl[(size_t)(t0+i)*96 + dir*48 + r];
    }
    __syncthreads();
    const float* wp = dtwl + dir*(4*512*16) + (size_t)tid * 16;
    float4 w0 = *(const float4*)(wp);
    float4 w1 = *(const float4*)(wp+4);
    float4 w2 = *(const float4*)(wp+8);
    float4 w3 = *(const float4*)(wp+12);
    float bia = dtbl[dir*(4*512) + tid];
    #pragma unroll
    for (int i = 0; i < 16; i++) {
        const float* ds = dsh[i];
        float a = bia;
        a += ds[0]*w0.x + ds[1]*w0.y + ds[2]*w0.z + ds[3]*w0.w;
        a += ds[4]*w1.x + ds[5]*w1.y + ds[6]*w1.z + ds[7]*w1.w;
        a += ds[8]*w2.x + ds[9]*w2.y + ds[10]*w2.z + ds[11]*w2.w;
        a += ds[12]*w3.x + ds[13]*w3.y + ds[14]*w3.z + ds[15]*w3.w;
        dto[(size_t)(t0+i)*1024 + dir*512 + tid] = softplusf(a);
    }
}

#define LOG2E 1.442695040888963f

// ---------------- selective scan: pass 1 (per-chunk local scan, both dirs) ----------------
__global__ __launch_bounds__(128) void k_scan1(
    const float* __restrict__ dt, const float* __restrict__ xs,
    const float* __restrict__ dbl, const float* __restrict__ alogl,
    float* __restrict__ hend, float* __restrict__ sumdt)
{
    int d = blockIdx.x * 128 + threadIdx.x;
    int c = blockIdx.y;
    int z = blockIdx.z;
    int b = z >> 1, dir = z & 1;
    __shared__ float Bsh[CS][16];
    int s0 = c * CS;
    for (int idx = threadIdx.x; idx < CS*16; idx += 128) {
        int i = idx >> 4, n = idx & 15;
        int t = dir ? (1023 - (s0+i)) : (s0+i);
        Bsh[i][n] = dbl[(size_t)(b*1024 + t)*96 + dir*48 + 16 + n];
    }
    __syncthreads();
    const float* ap = alogl + dir*(4*512*16) + (size_t)d*16;
    float A2[16];
    #pragma unroll
    for (int n = 0; n < 16; n++) A2[n] = -__expf(ap[n]) * LOG2E;
    float h[16];
    #pragma unroll
    for (int n = 0; n < 16; n++) h[n] = 0.f;
    float sd = 0.f;
    int col = dir*512 + d;
    for (int i = 0; i < CS; i++) {
        int t = dir ? (1023 - (s0+i)) : (s0+i);
        size_t off = (size_t)(b*1024 + t)*1024 + col;
        float dtv = dt[off];
        float xv  = xs[off];
        float w = dtv * xv;
        sd += dtv;
        #pragma unroll
        for (int n = 0; n < 16; n++)
            h[n] = ex2f(dtv * A2[n]) * h[n] + w * Bsh[i][n];
    }
    int bdd = (b << 10) + (dir << 9) + d;
    sumdt[(size_t)bdd*NC + c] = sd;
    #pragma unroll
    for (int n = 0; n < 16; n++)
        hend[((size_t)bdd*NC + c)*16 + n] = h[n];
}

// ---------------- selective scan: pass 2 (chunk carry, both dirs) ----------------
__global__ __launch_bounds__(256) void k_scan2(
    const float* __restrict__ hend, const float* __restrict__ sumdt,
    const float* __restrict__ alogl, float* __restrict__ hinit)
{
    int bdd = blockIdx.x * 256 + threadIdx.x;   // 8192
    int d = bdd & 511;
    int dir = (bdd >> 9) & 1;
    const float* ap = alogl + dir*(4*512*16) + (size_t)d*16;
    float A2[16];
    #pragma unroll
    for (int n = 0; n < 16; n++) A2[n] = -__expf(ap[n]) * LOG2E;
    float H[16];
    #pragma unroll
    for (int n = 0; n < 16; n++) H[n] = 0.f;
    for (int c = 0; c < NC; c++) {
        #pragma unroll
        for (int n = 0; n < 16; n++)
            hinit[((size_t)bdd*NC + c)*16 + n] = H[n];
        float sd = sumdt[(size_t)bdd*NC + c];
        #pragma unroll
        for (int n = 0; n < 16; n++)
            H[n] = ex2f(A2[n]*sd) * H[n] + hend[((size_t)bdd*NC + c)*16 + n];
    }
}

// ---------------- selective scan: pass 3 (rescan + fused gate epilogue, both dirs) ---------
__global__ __launch_bounds__(128) void k_scan3(
    const float* __restrict__ dt, const float* __restrict__ xs,
    const float* __restrict__ dbl, const float* __restrict__ xz,
    const float* __restrict__ alogl, const float* __restrict__ dpl,
    const float* __restrict__ hinit, float* __restrict__ y)
{
    int d = blockIdx.x * 128 + threadIdx.x;
    int c = blockIdx.y;
    int z = blockIdx.z;
    int b = z >> 1, dir = z & 1;
    __shared__ float sh[CS][32];   // [i][0..15]=B, [i][16..31]=C
    int s0 = c * CS;
    for (int idx = threadIdx.x; idx < CS*32; idx += 128) {
        int i = idx >> 5, q = idx & 31;
        int t = dir ? (1023 - (s0+i)) : (s0+i);
        sh[i][q] = dbl[(size_t)(b*1024 + t)*96 + dir*48 + 16 + q];
    }
    __syncthreads();
    const float* ap = alogl + dir*(4*512*16) + (size_t)d*16;
    float A2[16];
    #pragma unroll
    for (int n = 0; n < 16; n++) A2[n] = -__expf(ap[n]) * LOG2E;
    int bdd = (b << 10) + (dir << 9) + d;
    float h[16];
    #pragma unroll
    for (int n = 0; n < 16; n++) h[n] = hinit[((size_t)bdd*NC + c)*16 + n];
    float dpd = dpl[dir*(4*512) + d];
    int col = dir*512 + d;
    for (int i = 0; i < CS; i++) {
        int t = dir ? (1023 - (s0+i)) : (s0+i);
        size_t off = (size_t)(b*1024 + t)*1024 + col;
        float dtv = dt[off];
        float xv  = xs[off];
        float w = dtv * xv;
        float yv = 0.f;
        #pragma unroll
        for (int n = 0; n < 16; n++) {
            h[n] = ex2f(dtv * A2[n]) * h[n] + w * sh[i][n];
            yv += h[n] * sh[i][16 + n];
        }
        float zv = xz[(size_t)(b*1024 + t)*2048 + dir*1024 + 512 + d];
        y[off] = (yv + dpd * xv) * siluf(zv);
    }
}

// ---------------- combine: dual residual LN + halve, with time-reversal fold ----------------
__global__ __launch_bounds__(256) void k_combine(
    const float* __restrict__ yF, const float* __restrict__ yB,
    const float* __restrict__ feat,
    const float* __restrict__ g, const float* __restrict__ bta,
    float* __restrict__ outf)
{
    int bt = blockIdx.x, tid = threadIdx.x;
    int b = bt >> 10, t = bt & 1023;
    int btr = (b << 10) + (1023 - t);
    __shared__ float red[8];
    float v1 = yF[(size_t)bt*DM + tid] + feat[(size_t)bt*DM + tid];
    float v2 = yB[(size_t)bt*DM + tid] + feat[(size_t)btr*DM + tid];
    float s1 = block_reduce_sum256(v1, red);
    float m1 = s1 * (1.f/256.f);
    float d1 = v1 - m1;
    float q1 = block_reduce_sum256(d1*d1, red);
    float i1 = rsqrtf(q1 * (1.f/256.f) + 1e-5f);
    float s2 = block_reduce_sum256(v2, red);
    float m2 = s2 * (1.f/256.f);
    float d2 = v2 - m2;
    float q2 = block_reduce_sum256(d2*d2, red);
    float i2 = rsqrtf(q2 * (1.f/256.f) + 1e-5f);
    outf[(size_t)bt*DM + tid] = 0.5f * (d1*i1 + d2*i2) * g[tid] + bta[tid];
}

// ---------------- final mean over L ----------------
__global__ __launch_bounds__(256) void k_mean(const float* __restrict__ feat, float* __restrict__ out) {
    int b = blockIdx.x, i = threadIdx.x;
    float s = 0.f;
    const float* p = feat + (size_t)b*1024*DM + i;
    for (int t = 0; t < 1024; t++) s += p[(size_t)t*DM];
    out[(size_t)b*DM + i] = s * (1.f/1024.f);
}

// ---------------- host launcher ----------------
extern "C" void kernel_launch(void* const* d_in, const int* in_sizes, int n_in,
                              void* d_out, int out_size) {
    const float* x         = (const float*)d_in[0];
    const float* emb_proto = (const float*)d_in[1];
    const float* emb_flags = (const float*)d_in[2];
    const float* emb_dir   = (const float*)d_in[3];
    const float* len_w     = (const float*)d_in[4];
    const float* len_b     = (const float*)d_in[5];
    const float* iat_w     = (const float*)d_in[6];
    const float* iat_b     = (const float*)d_in[7];
    const float* fus_w     = (const float*)d_in[8];
    const float* fus_b     = (const float*)d_in[9];
    const float* tok_g     = (const float*)d_in[10];
    const float* tok_b     = (const float*)d_in[11];
    const float* in_proj_w = (const float*)d_in[12];
    const float* conv_w    = (const float*)d_in[13];
    const float* conv_b    = (const float*)d_in[14];
    const float* xproj_w   = (const float*)d_in[15];
    const float* dt_w      = (const float*)d_in[16];
    const float* dt_b      = (const float*)d_in[17];
    const float* A_log     = (const float*)d_in[18];
    const float* D_p       = (const float*)d_in[19];
    const float* out_w     = (const float*)d_in[20];
    const float* norm_g    = (const float*)d_in[21];
    const float* norm_b    = (const float*)d_in[22];
    float* out = (float*)d_out;

    float *featA, *featB, *xz, *xs, *dbl, *dtb, *ybuf, *yF, *yB, *hend, *sumdt, *hinit;
    cudaGetSymbolAddress((void**)&featA, g_featA);
    cudaGetSymbolAddress((void**)&featB, g_featB);
    cudaGetSymbolAddress((void**)&xz,    g_xz);
    cudaGetSymbolAddress((void**)&xs,    g_xs);
    cudaGetSymbolAddress((void**)&dbl,   g_dbl);
    cudaGetSymbolAddress((void**)&dtb,   g_dtv);
    cudaGetSymbolAddress((void**)&ybuf,  g_y);
    cudaGetSymbolAddress((void**)&yF,    g_yF);
    cudaGetSymbolAddress((void**)&yB,    g_yB);
    cudaGetSymbolAddress((void**)&hend,  g_hend);
    cudaGetSymbolAddress((void**)&sumdt, g_sumdt);
    cudaGetSymbolAddress((void**)&hinit, g_hinit);

    k_embed<<<NT, 256>>>(x, emb_proto, emb_flags, emb_dir, len_w, len_b,
                         iat_w, iat_b, fus_w, fus_b, tok_g, tok_b, featA);

    float* cur = featA;
    float* nxt = featB;
    const int BIG = 1 << 30;

    for (int l = 0; l < 4; l++) {
        const float* ipw0 = in_proj_w + (size_t)l * 1024 * 256;
        const float* ipw1 = in_proj_w + (size_t)(4 + l) * 1024 * 256;
        const float* cwl  = conv_w + (size_t)l * 512 * 4;
        const float* cbl  = conv_b + (size_t)l * 512;
        const float* dtwl = dt_w + (size_t)l * 512 * 16;
        const float* dtbl = dt_b + (size_t)l * 512;
        const float* alogl = A_log + (size_t)l * 512 * 16;
        const float* dpl   = D_p + (size_t)l * 512;

        // in_proj both dirs: [8192,256] x [2048,256]^T -> xz [8192,2048]
        sgemm_f2<<<dim3(32, 64), 256>>>(cur, 256, ipw0, ipw1, 1024,
                                        xz, xz + 1024, 1024, 2048, 2048, 256);
        // depthwise conv + silu, both dirs
        k_conv<<<(NT*1024)/256, 256>>>(xz, cwl, cbl, xs);
        // xproj per dir: [8192,512] x [48,512]^T -> dbl cols
        for (int dir = 0; dir < 2; dir++) {
            const float* xpw = xproj_w + (size_t)(dir*4 + l) * 48 * 512;
            sgemm_f2<<<dim3(1, 64), 256>>>(xs + dir*512, 1024, xpw, xpw, BIG,
                                           dbl + dir*48, dbl + dir*48, BIG, 96, 48, 512);
        }
        // dt projection + softplus, both dirs
        k_dt<<<dim3(NT/16, 2), 512>>>(dbl, dtwl, dtbl, dtb);
        // selective scan (3 passes), both dirs
        k_scan1<<<dim3(4, NC, 16), 128>>>(dtb, xs, dbl, alogl, hend, sumdt);
        k_scan2<<<32, 256>>>(hend, sumdt, alogl, hinit);
        k_scan3<<<dim3(4, NC, 16), 128>>>(dtb, xs, dbl, xz, alogl, dpl, hinit, ybuf);
        // out_proj per dir: [8192,512] x [256,512]^T -> yF / yB
        for (int dir = 0; dir < 2; dir++) {
            const float* ow = out_w + (size_t)(dir*4 + l) * 256 * 512;
            float* yd = dir ? yB : yF;
            sgemm_f2<<<dim3(4, 64), 256>>>(ybuf + dir*512, 1024, ow, ow, BIG,
                                           yd, yd, BIG, 256, 256, 512);
        }
        k_combine<<<NT, 256>>>(yF, yB, cur, norm_g, norm_b, nxt);
        float* tmp = cur; cur = nxt; nxt = tmp;
    }

    k_mean<<<Bb, 256>>>(cur, out);
}

// round 4
// speedup vs baseline: 1.5104x; 1.1483x over previous
#include <cuda_runtime.h>
#include <math.h>

#define Bb   8
#define Ls   1024
#define DM   256
#define DIc  512
#define NT   (Bb*Ls)      // 8192 tokens
#define CS   64           // scan chunk size
#define NC   (Ls/CS)      // 16 chunks
#define DSn  16

// ---------------- scratch (static device memory; no runtime allocs) ----------------
__device__ float g_featA[NT*DM];
__device__ float g_featB[NT*DM];
__device__ float g_xz  [NT*2048];      // merged dirs: cols [dir*1024 + (x:0..511 | z:512..1023)]
__device__ float g_xs  [NT*1024];      // merged dirs: cols [dir*512 + d]
__device__ float g_dbl [NT*96];        // merged dirs: cols [dir*48 + r]
__device__ float g_y   [NT*1024];      // merged dirs
__device__ float g_yFB [NT*512];       // cols [dir*256 + c]
__device__ float g_hend [8192*NC*DSn]; // bdd = b*1024 + dir*512 + d
__device__ float g_sumdt[8192*NC];
__device__ float g_hinit[8192*NC*DSn];

// ---------------- helpers ----------------
static __device__ __forceinline__ float ex2f(float v) {
    float r;
    asm("ex2.approx.f32 %0, %1;" : "=f"(r) : "f"(v));
    return r;
}
static __device__ __forceinline__ float siluf(float v) {
    return v / (1.f + __expf(-v));
}
static __device__ __forceinline__ float softplusf(float v) {
    return fmaxf(v, 0.f) + __logf(1.f + __expf(-fabsf(v)));
}
static __device__ __forceinline__ unsigned long long dup2(float w) {
    unsigned long long r;
    asm("mov.b64 %0, {%1, %1};" : "=l"(r) : "f"(w));
    return r;
}
static __device__ __forceinline__ void fma2(unsigned long long& d,
                                            unsigned long long a,
                                            unsigned long long b) {
    asm("fma.rn.f32x2 %0, %1, %2, %0;" : "+l"(d) : "l"(a), "l"(b));
}
static __device__ __forceinline__ float2 unpack2(unsigned long long v) {
    float2 f;
    asm("mov.b64 {%0, %1}, %2;" : "=f"(f.x), "=f"(f.y) : "l"(v));
    return f;
}

// block reduce over 256 threads (8 warps)
static __device__ __forceinline__ float block_reduce_sum256(float v, float* sh) {
    int tid = threadIdx.x;
    #pragma unroll
    for (int o = 16; o > 0; o >>= 1) v += __shfl_down_sync(0xffffffffu, v, o);
    if ((tid & 31) == 0) sh[tid >> 5] = v;
    __syncthreads();
    if (tid < 8) {
        v = sh[tid];
        #pragma unroll
        for (int o = 4; o > 0; o >>= 1) v += __shfl_down_sync(0xffu, v, o);
        if (tid == 0) sh[0] = v;
    }
    __syncthreads();
    float r = sh[0];
    __syncthreads();
    return r;
}

// ---------------- embedding + fusion + token LN ----------------
__global__ __launch_bounds__(256) void k_embed(
    const float* __restrict__ x,
    const float* __restrict__ ep, const float* __restrict__ ef, const float* __restrict__ ed,
    const float* __restrict__ lw, const float* __restrict__ lb,
    const float* __restrict__ iw, const float* __restrict__ ib,
    const float* __restrict__ fw, const float* __restrict__ fb,
    const float* __restrict__ tg, const float* __restrict__ tb,
    float* __restrict__ feat)
{
    int bt = blockIdx.x;
    int tid = threadIdx.x;
    __shared__ float c[136];
    __shared__ float red[8];
    const float* xr = x + (size_t)bt * 5;
    if (tid < 136) {
        float v;
        if (tid < 32) {
            int p = (int)xr[0]; p = p < 0 ? 0 : (p > 255 ? 255 : p);
            v = ep[p*32 + tid];
        } else if (tid < 64) {
            int e = tid - 32;
            v = xr[1]*lw[e] + lb[e];
        } else if (tid < 96) {
            int f = (int)xr[2]; f = f < 0 ? 0 : (f > 63 ? 63 : f);
            v = ef[f*32 + (tid - 64)];
        } else if (tid < 128) {
            int e = tid - 96;
            v = xr[3]*iw[e] + ib[e];
        } else {
            int dr = (int)xr[4]; dr = dr < 0 ? 0 : (dr > 1 ? 1 : dr);
            v = ed[dr*8 + (tid - 128)];
        }
        c[tid] = v;
    }
    __syncthreads();
    float acc = fb[tid];
    const float* wr = fw + (size_t)tid * 136;
    #pragma unroll 8
    for (int k = 0; k < 136; k++) acc += c[k] * wr[k];
    float s = block_reduce_sum256(acc, red);
    float m = s * (1.f/256.f);
    float dv = acc - m;
    float q = block_reduce_sum256(dv*dv, red);
    float inv = rsqrtf(q * (1.f/256.f) + 1e-5f);
    feat[(size_t)bt*DM + tid] = dv * inv * tg[tid] + tb[tid];
}

// ---------------- f32x2 SGEMM, double-buffered, dir-aware ----------------
// C[dir][M,Nd] = A[dir][M,K] * W[dir][Nd,K]^T
// grid.x = ntiles*2 (dir = blockIdx.x / ntiles), grid.y = M/128.
// A base += dir*adir, W base += dir*wdir, C base += dir*cdir (floats).
#define GLOAD(kt) do { int _k = (kt)*16;                                        \
    a0 = *(const float4*)&Arow[_k];                                             \
    a1 = *(const float4*)&Arow[_k + 4];                                         \
    wv = *(const float4*)&Wrow[_k]; } while (0)

#define SSTORE(AS, WS) do {                                                     \
    AS[acol+0][arow]=a0.x; AS[acol+1][arow]=a0.y;                               \
    AS[acol+2][arow]=a0.z; AS[acol+3][arow]=a0.w;                               \
    AS[acol+4][arow]=a1.x; AS[acol+5][arow]=a1.y;                               \
    AS[acol+6][arow]=a1.z; AS[acol+7][arow]=a1.w;                               \
    WS[wcol+0][wrow]=wv.x; WS[wcol+1][wrow]=wv.y;                               \
    WS[wcol+2][wrow]=wv.z; WS[wcol+3][wrow]=wv.w; } while (0)

#define TCOMP(AS, WS) do {                                                      \
    _Pragma("unroll")                                                           \
    for (int kk = 0; kk < 16; kk++) {                                           \
        ulonglong2 aA = *(const ulonglong2*)&AS[kk][ty*8];                      \
        ulonglong2 aB = *(const ulonglong2*)&AS[kk][ty*8 + 4];                  \
        float4 wf = *(const float4*)&WS[kk][tx*4];                              \
        unsigned long long wd0 = dup2(wf.x);                                    \
        unsigned long long wd1 = dup2(wf.y);                                    \
        unsigned long long wd2 = dup2(wf.z);                                    \
        unsigned long long wd3 = dup2(wf.w);                                    \
        fma2(acc[0][0], aA.x, wd0); fma2(acc[0][1], aA.x, wd1);                 \
        fma2(acc[0][2], aA.x, wd2); fma2(acc[0][3], aA.x, wd3);                 \
        fma2(acc[1][0], aA.y, wd0); fma2(acc[1][1], aA.y, wd1);                 \
        fma2(acc[1][2], aA.y, wd2); fma2(acc[1][3], aA.y, wd3);                 \
        fma2(acc[2][0], aB.x, wd0); fma2(acc[2][1], aB.x, wd1);                 \
        fma2(acc[2][2], aB.x, wd2); fma2(acc[2][3], aB.x, wd3);                 \
        fma2(acc[3][0], aB.y, wd0); fma2(acc[3][1], aB.y, wd1);                 \
        fma2(acc[3][2], aB.y, wd2); fma2(acc[3][3], aB.y, wd3);                 \
    } } while (0)

__global__ __launch_bounds__(256) void sgemm_f2(
    const float* __restrict__ A, int lda, int adir,
    const float* __restrict__ W, int wdir,
    float* __restrict__ C, int cdir, int ldc,
    int ntiles, int Nd, int K)
{
    __shared__ __align__(16) float As0[16][132], As1[16][132];
    __shared__ __align__(16) float Ws0[16][68],  Ws1[16][68];
    int tid = threadIdx.x;
    int dir = blockIdx.x / ntiles;
    int n0  = (blockIdx.x - dir*ntiles) * 64;
    int m0  = blockIdx.y * 128;
    int tx = tid & 15, ty = tid >> 4;
    int arow = tid >> 1, acol = (tid & 1) * 8;
    int wrow = tid >> 2, wcol = (tid & 3) * 4;

    const float* Arow = A + (size_t)dir*adir + (size_t)(m0 + arow)*lda + acol;
    int ng = n0 + wrow;
    bool wvalid = ng < Nd;
    const float* Wrow = W + (size_t)dir*wdir + (size_t)(wvalid ? ng : 0)*K + wcol;

    unsigned long long acc[4][4];
    #pragma unroll
    for (int p = 0; p < 4; p++)
        #pragma unroll
        for (int j = 0; j < 4; j++) acc[p][j] = 0ull;

    float4 a0, a1, wv;
    GLOAD(0);
    SSTORE(As0, Ws0);
    __syncthreads();

    int tiles = K >> 4;   // even for K=256/512
    for (int kt = 0; kt < tiles; kt += 2) {
        GLOAD(kt + 1);
        TCOMP(As0, Ws0);
        SSTORE(As1, Ws1);
        __syncthreads();
        bool more = (kt + 2) < tiles;
        if (more) GLOAD(kt + 2);
        TCOMP(As1, Ws1);
        if (more) {
            SSTORE(As0, Ws0);
            __syncthreads();
        }
    }

    float* Cb = C + (size_t)dir*cdir;
    int n = n0 + tx*4;
    if (n < Nd) {
        #pragma unroll
        for (int p = 0; p < 4; p++) {
            int m = m0 + ty*8 + 2*p;
            float2 v0 = unpack2(acc[p][0]);
            float2 v1 = unpack2(acc[p][1]);
            float2 v2 = unpack2(acc[p][2]);
            float2 v3 = unpack2(acc[p][3]);
            *(float4*)&Cb[(size_t)m*ldc + n]     = make_float4(v0.x, v1.x, v2.x, v3.x);
            *(float4*)&Cb[(size_t)(m+1)*ldc + n] = make_float4(v0.y, v1.y, v2.y, v3.y);
        }
    }
}

// ---------------- depthwise causal/anticausal conv + silu (both dirs, float4 over d) -------
__global__ __launch_bounds__(256) void k_conv(
    const float* __restrict__ xz, const float* __restrict__ cwl,
    const float* __restrict__ cbl, float* __restrict__ xs)
{
    int idx = blockIdx.x * 256 + threadIdx.x;   // NT*256 total, 4 d per thread
    int d4 = (idx & 255) * 4;                    // 0..1020
    int bt = idx >> 8;
    int dir = d4 >> 9;
    int dd  = d4 & 511;
    int b = bt >> 10, t = bt & 1023;
    const float* cw = cwl + dir*(4*512*4) + dd*4;
    float4 wA = *(const float4*)&cw[0];
    float4 wB = *(const float4*)&cw[4];
    float4 wC = *(const float4*)&cw[8];
    float4 wD = *(const float4*)&cw[12];
    float4 bia = *(const float4*)&cbl[dir*(4*512) + dd];
    const float* base = xz + (size_t)(b << 10) * 2048 + dir*1024 + dd;
    float4 acc = bia;
    #define ACC4(T, TAP) do { float4 xv = *(const float4*)&base[(size_t)(T)*2048]; \
        acc.x += xv.x * wA.TAP; acc.y += xv.y * wB.TAP;                             \
        acc.z += xv.z * wC.TAP; acc.w += xv.w * wD.TAP; } while (0)
    if (!dir) {
        if (t >= 3) ACC4(t-3, x);
        if (t >= 2) ACC4(t-2, y);
        if (t >= 1) ACC4(t-1, z);
        ACC4(t, w);
    } else {
        ACC4(t, w);
        if (t+1 < 1024) ACC4(t+1, z);
        if (t+2 < 1024) ACC4(t+2, y);
        if (t+3 < 1024) ACC4(t+3, x);
    }
    #undef ACC4
    float4 o;
    o.x = siluf(acc.x); o.y = siluf(acc.y); o.z = siluf(acc.z); o.w = siluf(acc.w);
    *(float4*)&xs[(size_t)bt*1024 + dir*512 + dd] = o;
}

#define LOG2E 1.442695040888963f

// dt dot-product helper: 16-wide dot of ds[0..15] with q0..q3 plus bias
#define DTDOT(ds) (bias                                                         \
    + (ds)[0]*q0.x + (ds)[1]*q0.y + (ds)[2]*q0.z + (ds)[3]*q0.w                 \
    + (ds)[4]*q1.x + (ds)[5]*q1.y + (ds)[6]*q1.z + (ds)[7]*q1.w                 \
    + (ds)[8]*q2.x + (ds)[9]*q2.y + (ds)[10]*q2.z + (ds)[11]*q2.w               \
    + (ds)[12]*q3.x + (ds)[13]*q3.y + (ds)[14]*q3.z + (ds)[15]*q3.w)

// ---------------- selective scan: pass 1 (per-chunk local scan + fused dt) ----------------
__global__ __launch_bounds__(128) void k_scan1(
    const float* __restrict__ xs, const float* __restrict__ dbl,
    const float* __restrict__ dtwl, const float* __restrict__ dtbl,
    const float* __restrict__ alogl,
    float* __restrict__ hend, float* __restrict__ sumdt)
{
    int d = blockIdx.x * 128 + threadIdx.x;
    int c = blockIdx.y;
    int z = blockIdx.z;
    int b = z >> 1, dir = z & 1;
    __shared__ float Dsh[CS][32];   // [0..15]=dt feats, [16..31]=B
    int s0c = c * CS;
    for (int idx = threadIdx.x; idx < CS*32; idx += 128) {
        int i = idx >> 5, q = idx & 31;
        int t = dir ? (1023 - (s0c+i)) : (s0c+i);
        Dsh[i][q] = dbl[(size_t)(b*1024 + t)*96 + dir*48 + q];
    }
    __syncthreads();
    const float* ap = alogl + dir*(4*512*16) + (size_t)d*16;
    float A2[16];
    #pragma unroll
    for (int n = 0; n < 16; n++) A2[n] = -__expf(ap[n]) * LOG2E;
    const float* wp = dtwl + dir*(4*512*16) + (size_t)d*16;
    float4 q0 = *(const float4*)(wp);
    float4 q1 = *(const float4*)(wp+4);
    float4 q2 = *(const float4*)(wp+8);
    float4 q3 = *(const float4*)(wp+12);
    float bias = dtbl[dir*(4*512) + d];
    float h[16];
    #pragma unroll
    for (int n = 0; n < 16; n++) h[n] = 0.f;
    float sd = 0.f;
    int col = dir*512 + d;
    for (int i = 0; i < CS; i++) {
        int t = dir ? (1023 - (s0c+i)) : (s0c+i);
        const float* ds = Dsh[i];
        float dtv = softplusf(DTDOT(ds));
        float xv = xs[(size_t)(b*1024 + t)*1024 + col];
        float w = dtv * xv;
        sd += dtv;
        #pragma unroll
        for (int n = 0; n < 16; n++)
            h[n] = ex2f(dtv * A2[n]) * h[n] + w * ds[16 + n];
    }
    int bdd = (b << 10) + (dir << 9) + d;
    sumdt[(size_t)bdd*NC + c] = sd;
    #pragma unroll
    for (int n = 0; n < 16; n++)
        hend[((size_t)bdd*NC + c)*16 + n] = h[n];
}

// ---------------- selective scan: pass 2 (chunk carry, both dirs) ----------------
__global__ __launch_bounds__(256) void k_scan2(
    const float* __restrict__ hend, const float* __restrict__ sumdt,
    const float* __restrict__ alogl, float* __restrict__ hinit)
{
    int bdd = blockIdx.x * 256 + threadIdx.x;   // 8192
    int d = bdd & 511;
    int dir = (bdd >> 9) & 1;
    const float* ap = alogl + dir*(4*512*16) + (size_t)d*16;
    float A2[16];
    #pragma unroll
    for (int n = 0; n < 16; n++) A2[n] = -__expf(ap[n]) * LOG2E;
    float H[16];
    #pragma unroll
    for (int n = 0; n < 16; n++) H[n] = 0.f;
    for (int c = 0; c < NC; c++) {
        #pragma unroll
        for (int n = 0; n < 16; n++)
            hinit[((size_t)bdd*NC + c)*16 + n] = H[n];
        float sd = sumdt[(size_t)bdd*NC + c];
        #pragma unroll
        for (int n = 0; n < 16; n++)
            H[n] = ex2f(A2[n]*sd) * H[n] + hend[((size_t)bdd*NC + c)*16 + n];
    }
}

// ---------------- selective scan: pass 3 (rescan + fused dt + gate epilogue) ---------------
__global__ __launch_bounds__(128) void k_scan3(
    const float* __restrict__ xs, const float* __restrict__ dbl,
    const float* __restrict__ xz,
    const float* __restrict__ dtwl, const float* __restrict__ dtbl,
    const float* __restrict__ alogl, const float* __restrict__ dpl,
    const float* __restrict__ hinit, float* __restrict__ y)
{
    int d = blockIdx.x * 128 + threadIdx.x;
    int c = blockIdx.y;
    int z = blockIdx.z;
    int b = z >> 1, dir = z & 1;
    __shared__ float Dsh[CS][48];   // [0..15]=dt feats, [16..31]=B, [32..47]=C
    int s0c = c * CS;
    for (int idx = threadIdx.x; idx < CS*48; idx += 128) {
        int i = idx / 48, q = idx - i*48;
        int t = dir ? (1023 - (s0c+i)) : (s0c+i);
        Dsh[i][q] = dbl[(size_t)(b*1024 + t)*96 + dir*48 + q];
    }
    __syncthreads();
    const float* ap = alogl + dir*(4*512*16) + (size_t)d*16;
    float A2[16];
    #pragma unroll
    for (int n = 0; n < 16; n++) A2[n] = -__expf(ap[n]) * LOG2E;
    const float* wp = dtwl + dir*(4*512*16) + (size_t)d*16;
    float4 q0 = *(const float4*)(wp);
    float4 q1 = *(const float4*)(wp+4);
    float4 q2 = *(const float4*)(wp+8);
    float4 q3 = *(const float4*)(wp+12);
    float bias = dtbl[dir*(4*512) + d];
    int bdd = (b << 10) + (dir << 9) + d;
    float h[16];
    #pragma unroll
    for (int n = 0; n < 16; n++) h[n] = hinit[((size_t)bdd*NC + c)*16 + n];
    float dpd = dpl[dir*(4*512) + d];
    int col = dir*512 + d;
    for (int i = 0; i < CS; i++) {
        int t = dir ? (1023 - (s0c+i)) : (s0c+i);
        const float* ds = Dsh[i];
        float dtv = softplusf(DTDOT(ds));
        size_t off = (size_t)(b*1024 + t)*1024 + col;
        float xv = xs[off];
        float w = dtv * xv;
        float yv = 0.f;
        #pragma unroll
        for (int n = 0; n < 16; n++) {
            h[n] = ex2f(dtv * A2[n]) * h[n] + w * ds[16 + n];
            yv += h[n] * ds[32 + n];
        }
        float zv = xz[(size_t)(b*1024 + t)*2048 + dir*1024 + 512 + d];
        y[off] = (yv + dpd * xv) * siluf(zv);
    }
}

// ---------------- combine: dual residual LN + halve, with time-reversal fold ----------------
__global__ __launch_bounds__(256) void k_combine(
    const float* __restrict__ yFB,
    const float* __restrict__ feat,
    const float* __restrict__ g, const float* __restrict__ bta,
    float* __restrict__ outf)
{
    int bt = blockIdx.x, tid = threadIdx.x;
    int b = bt >> 10, t = bt & 1023;
    int btr = (b << 10) + (1023 - t);
    __shared__ float red[8];
    float v1 = yFB[(size_t)bt*512 + tid]       + feat[(size_t)bt*DM + tid];
    float v2 = yFB[(size_t)bt*512 + 256 + tid] + feat[(size_t)btr*DM + tid];
    float s1 = block_reduce_sum256(v1, red);
    float m1 = s1 * (1.f/256.f);
    float d1 = v1 - m1;
    float q1 = block_reduce_sum256(d1*d1, red);
    float i1 = rsqrtf(q1 * (1.f/256.f) + 1e-5f);
    float s2 = block_reduce_sum256(v2, red);
    float m2 = s2 * (1.f/256.f);
    float d2 = v2 - m2;
    float q2 = block_reduce_sum256(d2*d2, red);
    float i2 = rsqrtf(q2 * (1.f/256.f) + 1e-5f);
    outf[(size_t)bt*DM + tid] = 0.5f * (d1*i1 + d2*i2) * g[tid] + bta[tid];
}

// ---------------- final mean over L ----------------
__global__ __launch_bounds__(1024) void k_mean(const float* __restrict__ feat, float* __restrict__ out) {
    __shared__ float sh[4][256];
    int b = blockIdx.x;
    int col = threadIdx.x & 255, seg = threadIdx.x >> 8;
    float s = 0.f;
    const float* p = feat + ((size_t)b*1024 + seg*256)*DM + col;
    for (int t = 0; t < 256; t++) s += p[(size_t)t*DM];
    sh[seg][col] = s;
    __syncthreads();
    if (seg == 0)
        out[(size_t)b*DM + col] = (sh[0][col] + sh[1][col] + sh[2][col] + sh[3][col]) * (1.f/1024.f);
}

// ---------------- host launcher ----------------
extern "C" void kernel_launch(void* const* d_in, const int* in_sizes, int n_in,
                              void* d_out, int out_size) {
    const float* x         = (const float*)d_in[0];
    const float* emb_proto = (const float*)d_in[1];
    const float* emb_flags = (const float*)d_in[2];
    const float* emb_dir   = (const float*)d_in[3];
    const float* len_w     = (const float*)d_in[4];
    const float* len_b     = (const float*)d_in[5];
    const float* iat_w     = (const float*)d_in[6];
    const float* iat_b     = (const float*)d_in[7];
    const float* fus_w     = (const float*)d_in[8];
    const float* fus_b     = (const float*)d_in[9];
    const float* tok_g     = (const float*)d_in[10];
    const float* tok_b     = (const float*)d_in[11];
    const float* in_proj_w = (const float*)d_in[12];
    const float* conv_w    = (const float*)d_in[13];
    const float* conv_b    = (const float*)d_in[14];
    const float* xproj_w   = (const float*)d_in[15];
    const float* dt_w      = (const float*)d_in[16];
    const float* dt_b      = (const float*)d_in[17];
    const float* A_log     = (const float*)d_in[18];
    const float* D_p       = (const float*)d_in[19];
    const float* out_w     = (const float*)d_in[20];
    const float* norm_g    = (const float*)d_in[21];
    const float* norm_b    = (const float*)d_in[22];
    float* out = (float*)d_out;

    float *featA, *featB, *xz, *xs, *dbl, *ybuf, *yFB, *hend, *sumdt, *hinit;
    cudaGetSymbolAddress((void**)&featA, g_featA);
    cudaGetSymbolAddress((void**)&featB, g_featB);
    cudaGetSymbolAddress((void**)&xz,    g_xz);
    cudaGetSymbolAddress((void**)&xs,    g_xs);
    cudaGetSymbolAddress((void**)&dbl,   g_dbl);
    cudaGetSymbolAddress((void**)&ybuf,  g_y);
    cudaGetSymbolAddress((void**)&yFB,   g_yFB);
    cudaGetSymbolAddress((void**)&hend,  g_hend);
    cudaGetSymbolAddress((void**)&sumdt, g_sumdt);
    cudaGetSymbolAddress((void**)&hinit, g_hinit);

    k_embed<<<NT, 256>>>(x, emb_proto, emb_flags, emb_dir, len_w, len_b,
                         iat_w, iat_b, fus_w, fus_b, tok_g, tok_b, featA);

    float* cur = featA;
    float* nxt = featB;

    for (int l = 0; l < 4; l++) {
        const float* ipw  = in_proj_w + (size_t)l * 1024 * 256;
        const float* cwl  = conv_w + (size_t)l * 512 * 4;
        const float* cbl  = conv_b + (size_t)l * 512;
        const float* xpw  = xproj_w + (size_t)l * 48 * 512;
        const float* dtwl = dt_w + (size_t)l * 512 * 16;
        const float* dtbl = dt_b + (size_t)l * 512;
        const float* alogl = A_log + (size_t)l * 512 * 16;
        const float* dpl   = D_p + (size_t)l * 512;
        const float* ow    = out_w + (size_t)l * 256 * 512;

        // in_proj both dirs: A same, W per-dir, C cols dir*1024+n
        sgemm_f2<<<dim3(32, 64), 256>>>(cur, 256, 0, ipw, 4*1024*256,
                                        xz, 1024, 2048, 16, 1024, 256);
        // depthwise conv + silu, both dirs
        k_conv<<<NT, 256>>>(xz, cwl, cbl, xs);
        // xproj both dirs: A = xs + dir*512, W per-dir, C = dbl + dir*48
        sgemm_f2<<<dim3(2, 64), 256>>>(xs, 1024, 512, xpw, 4*48*512,
                                       dbl, 48, 96, 1, 48, 512);
        // selective scan (3 passes, dt fused), both dirs
        k_scan1<<<dim3(4, NC, 16), 128>>>(xs, dbl, dtwl, dtbl, alogl, hend, sumdt);
        k_scan2<<<32, 256>>>(hend, sumdt, alogl, hinit);
        k_scan3<<<dim3(4, NC, 16), 128>>>(xs, dbl, xz, dtwl, dtbl, alogl, dpl, hinit, ybuf);
        // out_proj both dirs: A = ybuf + dir*512, W per-dir, C = yFB + dir*256
        sgemm_f2<<<dim3(8, 64), 256>>>(ybuf, 1024, 512, ow, 4*256*512,
                                       yFB, 256, 512, 4, 256, 512);
        k_combine<<<NT, 256>>>(yFB, cur, norm_g, norm_b, nxt);
        float* tmp = cur; cur = nxt; nxt = tmp;
    }

    k_mean<<<Bb, 1024>>>(cur, out);
}